// round 2
// baseline (speedup 1.0000x reference)
#include <cuda_runtime.h>

// SCAConv: out[b,o,p] = sum_ikk xu[b,ikk,p] * (K[o,ikk] + adj[b,o,ikk,p]) + bias[o]
// with adj[b,o,ikk,p] = (h[b,p'] @ w2 + b2)[q'],  p' = o*16 + p/64, q' = (p%64)*576 + ikk.
// Folded through the contraction:
//   out[b,o,p] = K[o]·xu + sum_j h[b, o*16+t, j]*G[j] + Bb + bias[o]
//   G[j] = xu · w2[j, m*576:(m+1)*576],  Bb = xu · b2[m*576:(m+1)*576]
//   m = p%64 = (y&1)*32 + x,  t = p/64 = y/2.
// One block per (b, x-column, y-parity): 16 pixels share one w2/b2 slice.
// Main GEMM per block: [96 x 576] @ [576 x 16], fp32 exact via fma.rn.f32x2.

#define NCH 64
#define IKK 576
#define HH 32
#define WW 32
#define NP 1024
#define DH 32
#define BATCH 2
#define XS_STRIDE 580      // 576+4: float4-aligned; quarter-warp phases stay conflict-free
#define W2_STRIDE 36864    // OUT_CH * IKK

__device__ float g_h[BATCH * NP * DH];   // 256 KB scratch for MLP hidden activations

union F4U {
    float4 f4;
    unsigned long long u[2];
    float f[4];
};

__device__ __forceinline__ void ffma2(unsigned long long& d,
                                      unsigned long long a,
                                      unsigned long long b) {
    asm("fma.rn.f32x2 %0, %1, %2, %0;" : "+l"(d) : "l"(a), "l"(b));
}

// ---------------------------------------------------------------------------
// Kernel 1: h[b,pp,:] = silu([gx/32, gy/32, c[b]] @ w1 + b1), gx=pp/32, gy=pp%32
// ---------------------------------------------------------------------------
__global__ void mlp_h_kernel(const float* __restrict__ c,
                             const float* __restrict__ w1,
                             const float* __restrict__ b1) {
    int idx = blockIdx.x * blockDim.x + threadIdx.x;
    if (idx >= BATCH * NP) return;
    int b = idx >> 10;
    int pp = idx & (NP - 1);
    float feat[10];
    feat[0] = (float)(pp >> 5) * 0.03125f;   // gx / Wo
    feat[1] = (float)(pp & 31) * 0.03125f;   // gy / Ho
#pragma unroll
    for (int k = 0; k < 8; k++) feat[2 + k] = c[b * 8 + k];
    float* hout = &g_h[(b * NP + pp) * DH];
#pragma unroll 8
    for (int k = 0; k < DH; k++) {
        float z = b1[k];
#pragma unroll
        for (int d = 0; d < 10; d++) z = fmaf(feat[d], w1[d * DH + k], z);
        hout[k] = z / (1.0f + __expf(-z));   // silu
    }
}

// ---------------------------------------------------------------------------
// Kernel 2: main fused kernel. 128 threads: tx in 0..7 (pixels tx, tx+8),
// ty in 0..15 (rows ty, ty+16, ty+32, ty+48 of Kw; rows ty, ty+16 of w2-slice).
// ---------------------------------------------------------------------------
__global__ __launch_bounds__(128) void sca_main_kernel(
    const float* __restrict__ x,     // [B, 64, 32, 32]
    const float* __restrict__ Kw,    // [64, 576]
    const float* __restrict__ bias,  // [64]
    const float* __restrict__ w2,    // [32, 36864]
    const float* __restrict__ b2,    // [36864]
    float* __restrict__ out)         // [B, 64, 32, 32]
{
    __shared__ float xus[16 * XS_STRIDE];   // patch matrix X[t][ikk], 16 pixels
    __shared__ float res[97 * 17];          // row-dot results [97 rows][16 px], padded

    const int xcol = blockIdx.x;   // 0..31
    const int yp   = blockIdx.y;   // 0..1
    const int b    = blockIdx.z;   // 0..1
    const int tid  = threadIdx.x;  // 0..127
    const int m    = yp * 32 + xcol;

    // ---- Build unfold patches for the 16 pixels (y = 2t+yp, x = xcol) ----
    const float* xb = x + b * NCH * HH * WW;
    for (int i = tid; i < 16 * IKK; i += 128) {
        int t   = i / IKK;
        int ikk = i - t * IKK;
        int cch = ikk / 9;
        int r9  = ikk - cch * 9;
        int dy  = r9 / 3;
        int dx  = r9 - dy * 3;
        int yy  = 2 * t + yp + dy - 1;
        int xx  = xcol + dx - 1;
        float v = 0.0f;
        if (yy >= 0 && yy < HH && xx >= 0 && xx < WW)
            v = xb[cch * (HH * WW) + yy * WW + xx];
        xus[t * XS_STRIDE + ikk] = v;
    }
    __syncthreads();

    const int tx = tid & 7;    // pixel pair (tx, tx+8)
    const int ty = tid >> 3;   // 0..15

    const float4* wr0 = (const float4*)(Kw + ty * IKK);
    const float4* wr1 = (const float4*)(Kw + (ty + 16) * IKK);
    const float4* wr2 = (const float4*)(Kw + (ty + 32) * IKK);
    const float4* wr3 = (const float4*)(Kw + (ty + 48) * IKK);
    const float4* wr4 = (const float4*)(w2 + ty * W2_STRIDE + m * IKK);
    const float4* wr5 = (const float4*)(w2 + (ty + 16) * W2_STRIDE + m * IKK);
    const float4* xpa = (const float4*)(&xus[tx * XS_STRIDE]);
    const float4* xpb = (const float4*)(&xus[(tx + 8) * XS_STRIDE]);

    unsigned long long acc[6][2];
#pragma unroll
    for (int r = 0; r < 6; r++) { acc[r][0] = 0ull; acc[r][1] = 0ull; }

#pragma unroll 2
    for (int q = 0; q < IKK / 4; q++) {
        F4U xa, xbv;
        xa.f4  = xpa[q];
        xbv.f4 = xpb[q];
        F4U w0, w1v, w2v, w3, w4, w5;
        w0.f4  = __ldg(wr0 + q);
        w1v.f4 = __ldg(wr1 + q);
        w2v.f4 = __ldg(wr2 + q);
        w3.f4  = __ldg(wr3 + q);
        w4.f4  = __ldg(wr4 + q);
        w5.f4  = __ldg(wr5 + q);

        ffma2(acc[0][0], w0.u[0],  xa.u[0]);  ffma2(acc[0][0], w0.u[1],  xa.u[1]);
        ffma2(acc[0][1], w0.u[0],  xbv.u[0]); ffma2(acc[0][1], w0.u[1],  xbv.u[1]);
        ffma2(acc[1][0], w1v.u[0], xa.u[0]);  ffma2(acc[1][0], w1v.u[1], xa.u[1]);
        ffma2(acc[1][1], w1v.u[0], xbv.u[0]); ffma2(acc[1][1], w1v.u[1], xbv.u[1]);
        ffma2(acc[2][0], w2v.u[0], xa.u[0]);  ffma2(acc[2][0], w2v.u[1], xa.u[1]);
        ffma2(acc[2][1], w2v.u[0], xbv.u[0]); ffma2(acc[2][1], w2v.u[1], xbv.u[1]);
        ffma2(acc[3][0], w3.u[0],  xa.u[0]);  ffma2(acc[3][0], w3.u[1],  xa.u[1]);
        ffma2(acc[3][1], w3.u[0],  xbv.u[0]); ffma2(acc[3][1], w3.u[1],  xbv.u[1]);
        ffma2(acc[4][0], w4.u[0],  xa.u[0]);  ffma2(acc[4][0], w4.u[1],  xa.u[1]);
        ffma2(acc[4][1], w4.u[0],  xbv.u[0]); ffma2(acc[4][1], w4.u[1],  xbv.u[1]);
        ffma2(acc[5][0], w5.u[0],  xa.u[0]);  ffma2(acc[5][0], w5.u[1],  xa.u[1]);
        ffma2(acc[5][1], w5.u[0],  xbv.u[0]); ffma2(acc[5][1], w5.u[1],  xbv.u[1]);
    }

    // rows 0..63 = conv terms (o = ty + 16r), rows 64..95 = G[j = ty + 16(r-4)]
#pragma unroll
    for (int r = 0; r < 6; r++) {
        int row = (r < 4) ? (ty + 16 * r) : (64 + ty + 16 * (r - 4));
#pragma unroll
        for (int px = 0; px < 2; px++) {
            F4U u; u.u[0] = acc[r][px]; u.u[1] = 0ull;
            res[row * 17 + tx + 8 * px] = u.f[0] + u.f[1];
        }
    }

    // ---- Bb row: xu . b2slice, 8 lanes per pixel + butterfly reduce ----
    {
        int t = tid >> 3, seg = tid & 7;
        const float4* bp  = (const float4*)(b2 + m * IKK);
        const float4* xt2 = (const float4*)(&xus[t * XS_STRIDE]);
        float s = 0.f;
#pragma unroll
        for (int q = seg * 18; q < seg * 18 + 18; q++) {
            float4 xv = xt2[q];
            float4 bv = __ldg(bp + q);
            s += xv.x * bv.x + xv.y * bv.y + xv.z * bv.z + xv.w * bv.w;
        }
        s += __shfl_xor_sync(0xffffffffu, s, 1);
        s += __shfl_xor_sync(0xffffffffu, s, 2);
        s += __shfl_xor_sync(0xffffffffu, s, 4);
        if (seg == 0) res[96 * 17 + t] = s;
    }
    __syncthreads();

    // ---- Epilogue: out[b,o,p] = conv + h[b,o*16+t,:].G[:,t] + Bb + bias ----
    const float* hb = &g_h[b * NP * DH];
#pragma unroll
    for (int e = tid; e < 1024; e += 128) {
        int o = e >> 4;
        int t = e & 15;
        const float4* hp = (const float4*)(hb + (o * 16 + t) * DH);
        float vacc0 = 0.f, vacc1 = 0.f;
#pragma unroll
        for (int q = 0; q < 8; q++) {
            float4 hv = __ldg(hp + q);
            vacc0 = fmaf(hv.x, res[(64 + q * 4 + 0) * 17 + t], vacc0);
            vacc1 = fmaf(hv.y, res[(64 + q * 4 + 1) * 17 + t], vacc1);
            vacc0 = fmaf(hv.z, res[(64 + q * 4 + 2) * 17 + t], vacc0);
            vacc1 = fmaf(hv.w, res[(64 + q * 4 + 3) * 17 + t], vacc1);
        }
        float val = res[o * 17 + t] + res[96 * 17 + t] + bias[o] + vacc0 + vacc1;
        int p = (2 * t + yp) * 32 + xcol;
        out[((b * NCH + o) << 10) + p] = val;
    }
}

// ---------------------------------------------------------------------------
extern "C" void kernel_launch(void* const* d_in, const int* in_sizes, int n_in,
                              void* d_out, int out_size) {
    const float* x    = (const float*)d_in[0];
    const float* c    = (const float*)d_in[1];
    const float* kern = (const float*)d_in[2];
    const float* bias = (const float*)d_in[3];
    const float* w1   = (const float*)d_in[4];
    const float* b1   = (const float*)d_in[5];
    const float* w2   = (const float*)d_in[6];
    const float* b2   = (const float*)d_in[7];
    float* out = (float*)d_out;

    mlp_h_kernel<<<8, 256>>>(c, w1, b1);

    dim3 grid(32, 2, BATCH);
    sca_main_kernel<<<grid, 128>>>(x, kern, bias, w2, b2, out);
}

// round 13
// speedup vs baseline: 1.2620x; 1.2620x over previous
#include <cuda_runtime.h>

// SCAConv: out[b,o,p] = sum_ikk xu[b,ikk,p] * (K[o,ikk] + adj[b,o,ikk,p]) + bias[o]
// with adj[b,o,ikk,p] = (h[b,p'] @ w2 + b2)[q'],  p' = o*16 + p/64, q' = (p%64)*576 + ikk.
// Folded through the contraction:
//   out[b,o,p] = K[o]·xu + sum_j h[b, o*16+t, j]*G[j] + Bb + bias[o]
//   G[j] = xu · w2[j, m*576:(m+1)*576],  Bb = xu · b2[m*576:(m+1)*576]
//   m = p%64 = (y&1)*32 + x,  t = p/64 = y/2.
// One block per (b, x-column, y-parity): 16 pixels share one w2/b2 slice.
// 512 threads: lane = (tx:3b pixel-pair, kc:2b split-k chunk), warp = ty row-group.
// Split-k partials reduced via shfl_xor over the kc lane bits.

#define NCH 64
#define IKK 576
#define HH 32
#define WW 32
#define NP 1024
#define DH 32
#define BATCH 2
#define XS_STRIDE 580      // 576+4: float4-aligned; quarter-warp phases conflict-free
#define W2_STRIDE 36864    // OUT_CH * IKK
#define KCHUNK 36          // 144 floats = 36 float4 per k-chunk

__device__ float g_h[BATCH * NP * DH];   // 256 KB scratch for MLP hidden activations

union F4U {
    float4 f4;
    unsigned long long u[2];
    float f[4];
};

union U64F2 {
    unsigned long long u;
    float f[2];
};

__device__ __forceinline__ void ffma2(unsigned long long& d,
                                      unsigned long long a,
                                      unsigned long long b) {
    asm("fma.rn.f32x2 %0, %1, %2, %0;" : "+l"(d) : "l"(a), "l"(b));
}

// ---------------------------------------------------------------------------
// Kernel 1: h[b,pp,:] = silu([gx/32, gy/32, c[b]] @ w1 + b1), gx=pp/32, gy=pp%32
// ---------------------------------------------------------------------------
__global__ void mlp_h_kernel(const float* __restrict__ c,
                             const float* __restrict__ w1,
                             const float* __restrict__ b1) {
    int idx = blockIdx.x * blockDim.x + threadIdx.x;
    if (idx >= BATCH * NP) return;
    int b = idx >> 10;
    int pp = idx & (NP - 1);
    float feat[10];
    feat[0] = (float)(pp >> 5) * 0.03125f;   // gx / Wo
    feat[1] = (float)(pp & 31) * 0.03125f;   // gy / Ho
#pragma unroll
    for (int k = 0; k < 8; k++) feat[2 + k] = c[b * 8 + k];
    float* hout = &g_h[(b * NP + pp) * DH];
#pragma unroll 8
    for (int k = 0; k < DH; k++) {
        float z = b1[k];
#pragma unroll
        for (int d = 0; d < 10; d++) z = fmaf(feat[d], w1[d * DH + k], z);
        hout[k] = z / (1.0f + __expf(-z));   // silu
    }
}

// ---------------------------------------------------------------------------
// Kernel 2: main fused kernel. 512 threads, 16 warps.
// ---------------------------------------------------------------------------
__global__ __launch_bounds__(512) void sca_main_kernel(
    const float* __restrict__ x,     // [B, 64, 32, 32]
    const float* __restrict__ Kw,    // [64, 576]
    const float* __restrict__ bias,  // [64]
    const float* __restrict__ w2,    // [32, 36864]
    const float* __restrict__ b2,    // [36864]
    float* __restrict__ out)         // [B, 64, 32, 32]
{
    __shared__ float xus[16 * XS_STRIDE];   // patch matrix X[t][ikk], 16 pixels
    __shared__ float res[97 * 17];          // row-dot results [97 rows][16 px], padded

    const int xcol = blockIdx.x;   // 0..31
    const int yp   = blockIdx.y;   // 0..1
    const int b    = blockIdx.z;   // 0..1
    const int tid  = threadIdx.x;  // 0..511
    const int m    = yp * 32 + xcol;

    // ---- Build unfold patches for the 16 pixels (y = 2t+yp, x = xcol) ----
    const float* xb = x + b * NCH * HH * WW;
    for (int i = tid; i < 16 * IKK; i += 512) {
        int t   = i / IKK;
        int ikk = i - t * IKK;
        int cch = ikk / 9;
        int r9  = ikk - cch * 9;
        int dy  = r9 / 3;
        int dx  = r9 - dy * 3;
        int yy  = 2 * t + yp + dy - 1;
        int xx  = xcol + dx - 1;
        float v = 0.0f;
        if (yy >= 0 && yy < HH && xx >= 0 && xx < WW)
            v = xb[cch * (HH * WW) + yy * WW + xx];
        xus[t * XS_STRIDE + ikk] = v;
    }
    __syncthreads();

    // Lane decomposition: tx = pixel pair (tx, tx+8); kc = split-k chunk; ty = warp/row-group
    const int tx = tid & 7;
    const int kc = (tid >> 3) & 3;
    const int ty = tid >> 5;           // 0..15

    const int ko = kc * KCHUNK;        // float4 offset of this k-chunk
    const float4* wr0 = (const float4*)(Kw + ty * IKK) + ko;
    const float4* wr1 = (const float4*)(Kw + (ty + 16) * IKK) + ko;
    const float4* wr2 = (const float4*)(Kw + (ty + 32) * IKK) + ko;
    const float4* wr3 = (const float4*)(Kw + (ty + 48) * IKK) + ko;
    const float4* wr4 = (const float4*)(w2 + ty * W2_STRIDE + m * IKK) + ko;
    const float4* wr5 = (const float4*)(w2 + (ty + 16) * W2_STRIDE + m * IKK) + ko;
    const float4* xpa = (const float4*)(&xus[tx * XS_STRIDE]) + ko;
    const float4* xpb = (const float4*)(&xus[(tx + 8) * XS_STRIDE]) + ko;

    unsigned long long acc[6][2];
#pragma unroll
    for (int r = 0; r < 6; r++) { acc[r][0] = 0ull; acc[r][1] = 0ull; }

#pragma unroll 4
    for (int q = 0; q < KCHUNK; q++) {
        F4U xa, xbv;
        xa.f4  = xpa[q];
        xbv.f4 = xpb[q];
        F4U w0, w1v, w2v, w3, w4, w5;
        w0.f4  = __ldg(wr0 + q);
        w1v.f4 = __ldg(wr1 + q);
        w2v.f4 = __ldg(wr2 + q);
        w3.f4  = __ldg(wr3 + q);
        w4.f4  = __ldg(wr4 + q);
        w5.f4  = __ldg(wr5 + q);

        ffma2(acc[0][0], w0.u[0],  xa.u[0]);  ffma2(acc[0][0], w0.u[1],  xa.u[1]);
        ffma2(acc[0][1], w0.u[0],  xbv.u[0]); ffma2(acc[0][1], w0.u[1],  xbv.u[1]);
        ffma2(acc[1][0], w1v.u[0], xa.u[0]);  ffma2(acc[1][0], w1v.u[1], xa.u[1]);
        ffma2(acc[1][1], w1v.u[0], xbv.u[0]); ffma2(acc[1][1], w1v.u[1], xbv.u[1]);
        ffma2(acc[2][0], w2v.u[0], xa.u[0]);  ffma2(acc[2][0], w2v.u[1], xa.u[1]);
        ffma2(acc[2][1], w2v.u[0], xbv.u[0]); ffma2(acc[2][1], w2v.u[1], xbv.u[1]);
        ffma2(acc[3][0], w3.u[0],  xa.u[0]);  ffma2(acc[3][0], w3.u[1],  xa.u[1]);
        ffma2(acc[3][1], w3.u[0],  xbv.u[0]); ffma2(acc[3][1], w3.u[1],  xbv.u[1]);
        ffma2(acc[4][0], w4.u[0],  xa.u[0]);  ffma2(acc[4][0], w4.u[1],  xa.u[1]);
        ffma2(acc[4][1], w4.u[0],  xbv.u[0]); ffma2(acc[4][1], w4.u[1],  xbv.u[1]);
        ffma2(acc[5][0], w5.u[0],  xa.u[0]);  ffma2(acc[5][0], w5.u[1],  xa.u[1]);
        ffma2(acc[5][1], w5.u[0],  xbv.u[0]); ffma2(acc[5][1], w5.u[1],  xbv.u[1]);
    }

    // ---- Reduce split-k partials over kc lanes (bits 3,4 of lane id) ----
#pragma unroll
    for (int r = 0; r < 6; r++) {
#pragma unroll
        for (int px = 0; px < 2; px++) {
            U64F2 u; u.u = acc[r][px];
            float s = u.f[0] + u.f[1];
            s += __shfl_xor_sync(0xffffffffu, s, 8);
            s += __shfl_xor_sync(0xffffffffu, s, 16);
            if (kc == 0) {
                int row = (r < 4) ? (ty + 16 * r) : (64 + ty + 16 * (r - 4));
                res[row * 17 + tx + 8 * px] = s;
            }
        }
    }

    // ---- Bb row: xu . b2slice, 8 lanes per pixel + butterfly reduce ----
    if (tid < 128) {
        int t = tid >> 3, seg = tid & 7;
        const float4* bp  = (const float4*)(b2 + m * IKK);
        const float4* xt2 = (const float4*)(&xus[t * XS_STRIDE]);
        float s = 0.f;
#pragma unroll
        for (int q = seg * 18; q < seg * 18 + 18; q++) {
            float4 xv = xt2[q];
            float4 bv = __ldg(bp + q);
            s += xv.x * bv.x + xv.y * bv.y + xv.z * bv.z + xv.w * bv.w;
        }
        s += __shfl_xor_sync(0xffffffffu, s, 1);
        s += __shfl_xor_sync(0xffffffffu, s, 2);
        s += __shfl_xor_sync(0xffffffffu, s, 4);
        if (seg == 0) res[96 * 17 + t] = s;
    }
    __syncthreads();

    // ---- Epilogue: out[b,o,p] = conv + h[b,o*16+t,:].G[:,t] + Bb + bias ----
    const float* hb = &g_h[b * NP * DH];
#pragma unroll
    for (int e = tid; e < 1024; e += 512) {
        int o = e >> 4;
        int t = e & 15;
        const float4* hp = (const float4*)(hb + (o * 16 + t) * DH);
        float vacc0 = 0.f, vacc1 = 0.f;
#pragma unroll
        for (int q = 0; q < 8; q++) {
            float4 hv = __ldg(hp + q);
            vacc0 = fmaf(hv.x, res[(64 + q * 4 + 0) * 17 + t], vacc0);
            vacc1 = fmaf(hv.y, res[(64 + q * 4 + 1) * 17 + t], vacc1);
            vacc0 = fmaf(hv.z, res[(64 + q * 4 + 2) * 17 + t], vacc0);
            vacc1 = fmaf(hv.w, res[(64 + q * 4 + 3) * 17 + t], vacc1);
        }
        float val = res[o * 17 + t] + res[96 * 17 + t] + bias[o] + vacc0 + vacc1;
        int p = (2 * t + yp) * 32 + xcol;
        out[((b * NCH + o) << 10) + p] = val;
    }
}

// ---------------------------------------------------------------------------
extern "C" void kernel_launch(void* const* d_in, const int* in_sizes, int n_in,
                              void* d_out, int out_size) {
    const float* x    = (const float*)d_in[0];
    const float* c    = (const float*)d_in[1];
    const float* kern = (const float*)d_in[2];
    const float* bias = (const float*)d_in[3];
    const float* w1   = (const float*)d_in[4];
    const float* b1   = (const float*)d_in[5];
    const float* w2   = (const float*)d_in[6];
    const float* b2   = (const float*)d_in[7];
    float* out = (float*)d_out;

    mlp_h_kernel<<<8, 256>>>(c, w1, b1);

    dim3 grid(32, 2, BATCH);
    sca_main_kernel<<<grid, 512>>>(x, kern, bias, w2, b2, out);
}